// round 10
// baseline (speedup 1.0000x reference)
#include <cuda_runtime.h>

#define NUM_LEVELS 16
#define TABLE_SZ   16384
#define CHUNKS     9
#define THREADS    1024
#define MAX_B      262144
#define TILE_PTS   2048

// floor(16 * 1.38^l) computed in double precision, exactly representable in f32
__constant__ float c_res[NUM_LEVELS] = {
    16.f, 22.f, 30.f, 42.f, 58.f, 80.f, 110.f, 152.f,
    210.f, 290.f, 400.f, 553.f, 763.f, 1053.f, 1453.f, 2005.f
};

// Scratch (allocation-free rule: __device__ globals)
__device__ float2 g_scr[NUM_LEVELS * MAX_B];         // [level][b] features (33.5 MB)

// ---------------------------------------------------------------- main
__device__ __forceinline__ void hash_point(const float2* __restrict__ s_tab,
                                           const float px, const float py,
                                           const float pz, const float res,
                                           float& ox, float& oy)
{
    // Interpolation weights use the UNSCALED position (faithful to source)
    const float wx = px - floorf(px);
    const float wy = py - floorf(py);
    const float wz = pz - floorf(pz);

    const float sx = res * px;
    const float sy = res * py;
    const float sz = res * pz;

    const int lx = __float2int_rd(sx);
    const int ly = __float2int_rd(sy);
    const int lz = __float2int_rd(sz);
    const int hx = __float2int_ru(sx);
    const int hy = __float2int_ru(sy);
    const int hz = __float2int_ru(sz);

    // int32 wraparound multiply == uint32 multiply (same bits);
    // python remainder by 16384 == & 16383 on two's complement
    const unsigned ay0 = 2654435761u * (unsigned)ly;
    const unsigned ay1 = 2654435761u * (unsigned)hy;
    const unsigned az0 = 805459861u  * (unsigned)lz;
    const unsigned az1 = 805459861u  * (unsigned)hz;

    const unsigned b00 = ay0 ^ az0;
    const unsigned b10 = ay1 ^ az0;
    const unsigned b01 = ay0 ^ az1;
    const unsigned b11 = ay1 ^ az1;
    const unsigned ux = (unsigned)lx;
    const unsigned vx = (unsigned)hx;

    // Corner order v0..v7: (0,0,0)(1,0,0)(1,1,0)(0,1,0)(0,0,1)(1,0,1)(1,1,1)(0,1,1)
    const float2 f0 = s_tab[(ux ^ b00) & 16383u];
    const float2 f1 = s_tab[(vx ^ b00) & 16383u];
    const float2 f2 = s_tab[(vx ^ b10) & 16383u];
    const float2 f3 = s_tab[(ux ^ b10) & 16383u];
    const float2 f4 = s_tab[(ux ^ b01) & 16383u];
    const float2 f5 = s_tab[(vx ^ b01) & 16383u];
    const float2 f6 = s_tab[(vx ^ b11) & 16383u];
    const float2 f7 = s_tab[(ux ^ b11) & 16383u];

    const float ex = 1.f - wx, ey = 1.f - wy, ez = 1.f - wz;
    const float w00 = ex * ey, w10 = wx * ey, w11 = wx * wy, w01 = ex * wy;
    const float c0 = w00 * ez, c1 = w10 * ez, c2 = w11 * ez, c3 = w01 * ez;
    const float c4 = w00 * wz, c5 = w10 * wz, c6 = w11 * wz, c7 = w01 * wz;

    float vxr = c0 * f0.x;
    vxr = fmaf(c1, f1.x, vxr);
    vxr = fmaf(c2, f2.x, vxr);
    vxr = fmaf(c3, f3.x, vxr);
    vxr = fmaf(c4, f4.x, vxr);
    vxr = fmaf(c5, f5.x, vxr);
    vxr = fmaf(c6, f6.x, vxr);
    vxr = fmaf(c7, f7.x, vxr);

    float vyr = c0 * f0.y;
    vyr = fmaf(c1, f1.y, vyr);
    vyr = fmaf(c2, f2.y, vyr);
    vyr = fmaf(c3, f3.y, vyr);
    vyr = fmaf(c4, f4.y, vyr);
    vyr = fmaf(c5, f5.y, vyr);
    vyr = fmaf(c6, f6.y, vyr);
    vyr = fmaf(c7, f7.y, vyr);

    ox = vxr;
    oy = vyr;
}

extern __shared__ unsigned char smem_raw[];

__global__ __launch_bounds__(THREADS, 1)
void hashenc_kernel(const float4* __restrict__ x4,
                    const float* __restrict__ tables, int B)
{
    float2* s_tab = reinterpret_cast<float2*>(smem_raw);                 // 128 KB
    float4* s_x4  = reinterpret_cast<float4*>(smem_raw + TABLE_SZ * 8);  // 24 KB

    const int level = blockIdx.y;

    // Cooperative fill of this level's table into shared memory (16B chunks)
    {
        const float4* src = reinterpret_cast<const float4*>(
            tables + (size_t)level * TABLE_SZ * 2);
        float4* dst = reinterpret_cast<float4*>(s_tab);
        #pragma unroll 4
        for (int i = threadIdx.x; i < TABLE_SZ / 2; i += THREADS)
            dst[i] = src[i];
    }

    const float res = c_res[level];
    const int per   = (B + gridDim.x - 1) / gridDim.x;  // 29128 (div by 8)
    const int start = blockIdx.x * per;
    const int end   = min(start + per, B);

    float2* __restrict__ scr = g_scr + (size_t)level * B;
    const float* sx = reinterpret_cast<const float*>(s_x4);

    for (int base = start; base < end; base += TILE_PTS) {
        const int len = min(TILE_PTS, end - base);      // always div by 4
        const int nf4 = (len * 3) >> 2;
        const float4* src = x4 + (((size_t)base * 3) >> 2);

        __syncthreads();   // protect previous tile's smem reads (and table fill)
        for (int k = threadIdx.x; k < nf4; k += THREADS)
            s_x4[k] = src[k];
        __syncthreads();

        const int lp = threadIdx.x;          // one pair per thread per tile
        if (2 * lp + 1 < len) {
            const float px0 = sx[6 * lp + 0];
            const float py0 = sx[6 * lp + 1];
            const float pz0 = sx[6 * lp + 2];
            const float px1 = sx[6 * lp + 3];
            const float py1 = sx[6 * lp + 4];
            const float pz1 = sx[6 * lp + 5];

            float ox0, oy0, ox1, oy1;
            hash_point(s_tab, px0, py0, pz0, res, ox0, oy0);
            hash_point(s_tab, px1, py1, pz1, res, ox1, oy1);

            // One coalesced STG.128 for the pair (base even -> 16B aligned)
            reinterpret_cast<float4*>(scr + base + 2 * lp)[0] =
                make_float4(ox0, oy0, ox1, oy1);
        }
    }
}

// ---------------------------------------------------------------- transpose
// Thread-per-point: 16 independent coalesced LDG.64 into registers (MLP=16),
// conflict-free STS.64 into s[16][257], then coalesced STG.128 out.
__global__ __launch_bounds__(256)
void transpose_kernel(float4* __restrict__ out4, int B)
{
    __shared__ float2 s[NUM_LEVELS][257];
    const int b0 = blockIdx.x * 256;
    const int t  = threadIdx.x;
    const int b  = b0 + t;

    if (b < B) {
        float2 v[NUM_LEVELS];
        #pragma unroll
        for (int l = 0; l < NUM_LEVELS; l++)
            v[l] = g_scr[(size_t)l * B + b];     // 16 independent loads in flight
        #pragma unroll
        for (int l = 0; l < NUM_LEVELS; l++)
            s[l][t] = v[l];                      // conflict-free
    }
    __syncthreads();

    // 256 points * 8 float4 = 2048 outputs, 8 per thread, coalesced
    #pragma unroll
    for (int i = 0; i < 8; i++) {
        int o = i * 256 + t;                     // 0..2047
        int p = o >> 3;
        int j = o & 7;
        if (b0 + p < B) {
            float2 a = s[2 * j + 0][p];
            float2 c = s[2 * j + 1][p];
            out4[(size_t)b0 * 8 + o] = make_float4(a.x, a.y, c.x, c.y);
        }
    }
}

extern "C" void kernel_launch(void* const* d_in, const int* in_sizes, int n_in,
                              void* d_out, int out_size)
{
    const float* x      = (const float*)d_in[0];
    const float* tables = (const float*)d_in[1];
    float4* out4        = (float4*)d_out;
    const int B = in_sizes[0] / 3;

    const int smem_main = TABLE_SZ * 8 + (TILE_PTS * 3 / 4) * 16;  // 131072+24576
    cudaFuncSetAttribute(hashenc_kernel,
                         cudaFuncAttributeMaxDynamicSharedMemorySize, smem_main);

    dim3 grid(CHUNKS, NUM_LEVELS);
    hashenc_kernel<<<grid, THREADS, smem_main>>>((const float4*)x, tables, B);

    transpose_kernel<<<(B + 255) / 256, 256>>>(out4, B);
}

// round 11
// speedup vs baseline: 1.1708x; 1.1708x over previous
#include <cuda_runtime.h>

#define NUM_LEVELS 16
#define TABLE_SZ   16384
#define CHUNKS     9
#define THREADS    1024
#define MAX_B      262144

// floor(16 * 1.38^l) computed in double precision, exactly representable in f32
__constant__ float c_res[NUM_LEVELS] = {
    16.f, 22.f, 30.f, 42.f, 58.f, 80.f, 110.f, 152.f,
    210.f, 290.f, 400.f, 553.f, 763.f, 1053.f, 1453.f, 2005.f
};

// Scratch (allocation-free rule: __device__ globals)
__device__ float4 g_xs[MAX_B];                       // packed positions (4 MB)
__device__ float2 g_scr[NUM_LEVELS * MAX_B];         // [level][b] features (33.5 MB)

extern __shared__ float2 s_tab[];  // main: 16384 float2 = 128 KB

// ---------------------------------------------------------------- pack x
__global__ __launch_bounds__(256)
void pack_x_kernel(const float4* __restrict__ x4, int B)
{
    __shared__ float sx[256 * 3];
    const int b0 = blockIdx.x * 256;
    const int t  = threadIdx.x;
    if (t < 192) {
        float4 v = x4[(size_t)(b0 * 3) / 4 + t];
        sx[4 * t + 0] = v.x; sx[4 * t + 1] = v.y;
        sx[4 * t + 2] = v.z; sx[4 * t + 3] = v.w;
    }
    __syncthreads();
    const int b = b0 + t;
    if (b < B)
        g_xs[b] = make_float4(sx[3 * t], sx[3 * t + 1], sx[3 * t + 2], 0.f);
}

// ---------------------------------------------------------------- main
__device__ __forceinline__ void hash_point(const float px, const float py,
                                           const float pz, const float res,
                                           float& ox, float& oy)
{
    // Interpolation weights use the UNSCALED position (faithful to source)
    const float wx = px - floorf(px);
    const float wy = py - floorf(py);
    const float wz = pz - floorf(pz);

    const float sx = res * px;
    const float sy = res * py;
    const float sz = res * pz;

    const int lx = __float2int_rd(sx);
    const int ly = __float2int_rd(sy);
    const int lz = __float2int_rd(sz);
    const int hx = __float2int_ru(sx);
    const int hy = __float2int_ru(sy);
    const int hz = __float2int_ru(sz);

    // int32 wraparound multiply == uint32 multiply (same bits);
    // python remainder by 16384 == & 16383 on two's complement
    const unsigned ay0 = 2654435761u * (unsigned)ly;
    const unsigned ay1 = 2654435761u * (unsigned)hy;
    const unsigned az0 = 805459861u  * (unsigned)lz;
    const unsigned az1 = 805459861u  * (unsigned)hz;

    const unsigned b00 = ay0 ^ az0;
    const unsigned b10 = ay1 ^ az0;
    const unsigned b01 = ay0 ^ az1;
    const unsigned b11 = ay1 ^ az1;
    const unsigned ux = (unsigned)lx;
    const unsigned vx = (unsigned)hx;

    // Corner order v0..v7: (0,0,0)(1,0,0)(1,1,0)(0,1,0)(0,0,1)(1,0,1)(1,1,1)(0,1,1)
    const float2 f0 = s_tab[(ux ^ b00) & 16383u];
    const float2 f1 = s_tab[(vx ^ b00) & 16383u];
    const float2 f2 = s_tab[(vx ^ b10) & 16383u];
    const float2 f3 = s_tab[(ux ^ b10) & 16383u];
    const float2 f4 = s_tab[(ux ^ b01) & 16383u];
    const float2 f5 = s_tab[(vx ^ b01) & 16383u];
    const float2 f6 = s_tab[(vx ^ b11) & 16383u];
    const float2 f7 = s_tab[(ux ^ b11) & 16383u];

    const float ex = 1.f - wx, ey = 1.f - wy, ez = 1.f - wz;
    const float w00 = ex * ey, w10 = wx * ey, w11 = wx * wy, w01 = ex * wy;
    const float c0 = w00 * ez, c1 = w10 * ez, c2 = w11 * ez, c3 = w01 * ez;
    const float c4 = w00 * wz, c5 = w10 * wz, c6 = w11 * wz, c7 = w01 * wz;

    float vxr = c0 * f0.x;
    vxr = fmaf(c1, f1.x, vxr);
    vxr = fmaf(c2, f2.x, vxr);
    vxr = fmaf(c3, f3.x, vxr);
    vxr = fmaf(c4, f4.x, vxr);
    vxr = fmaf(c5, f5.x, vxr);
    vxr = fmaf(c6, f6.x, vxr);
    vxr = fmaf(c7, f7.x, vxr);

    float vyr = c0 * f0.y;
    vyr = fmaf(c1, f1.y, vyr);
    vyr = fmaf(c2, f2.y, vyr);
    vyr = fmaf(c3, f3.y, vyr);
    vyr = fmaf(c4, f4.y, vyr);
    vyr = fmaf(c5, f5.y, vyr);
    vyr = fmaf(c6, f6.y, vyr);
    vyr = fmaf(c7, f7.y, vyr);

    ox = vxr;
    oy = vyr;
}

__global__ __launch_bounds__(THREADS, 1)
void hashenc_kernel(const float* __restrict__ tables, int B)
{
    const int level = blockIdx.y;

    // Cooperative fill of this level's table into shared memory (16B chunks)
    {
        const float4* src = reinterpret_cast<const float4*>(
            tables + (size_t)level * TABLE_SZ * 2);
        float4* dst = reinterpret_cast<float4*>(s_tab);
        #pragma unroll 4
        for (int i = threadIdx.x; i < TABLE_SZ / 2; i += THREADS)
            dst[i] = src[i];
    }
    __syncthreads();

    const float res = c_res[level];
    const int per   = (B + gridDim.x - 1) / gridDim.x;  // 29128 (even)
    const int start = blockIdx.x * per;
    const int end   = min(start + per, B);

    float2* __restrict__ scr = g_scr + (size_t)level * B;

    // Two consecutive points per thread; pairs never straddle chunk bounds
    for (int b = start + 2 * (int)threadIdx.x; b + 1 < end; b += 2 * THREADS) {
        const float4 p0 = g_xs[b];
        const float4 p1 = g_xs[b + 1];

        float ox0, oy0, ox1, oy1;
        hash_point(p0.x, p0.y, p0.z, res, ox0, oy0);
        hash_point(p1.x, p1.y, p1.z, res, ox1, oy1);

        // One coalesced STG.128 for the pair (b even -> 16B aligned)
        reinterpret_cast<float4*>(scr + b)[0] = make_float4(ox0, oy0, ox1, oy1);
    }
}

// ---------------------------------------------------------------- transpose
// Thread-per-point: 16 independent coalesced LDG.64 into registers (MLP=16),
// conflict-free STS.64 into s[16][257], then coalesced STG.128 out.
__global__ __launch_bounds__(256)
void transpose_kernel(float4* __restrict__ out4, int B)
{
    __shared__ float2 s[NUM_LEVELS][257];
    const int b0 = blockIdx.x * 256;
    const int t  = threadIdx.x;
    const int b  = b0 + t;

    if (b < B) {
        float2 v[NUM_LEVELS];
        #pragma unroll
        for (int l = 0; l < NUM_LEVELS; l++)
            v[l] = g_scr[(size_t)l * B + b];     // 16 independent loads in flight
        #pragma unroll
        for (int l = 0; l < NUM_LEVELS; l++)
            s[l][t] = v[l];                      // conflict-free
    }
    __syncthreads();

    // 256 points * 8 float4 = 2048 outputs, 8 per thread, coalesced
    #pragma unroll
    for (int i = 0; i < 8; i++) {
        int o = i * 256 + t;                     // 0..2047
        int p = o >> 3;
        int j = o & 7;
        if (b0 + p < B) {
            float2 a = s[2 * j + 0][p];
            float2 c = s[2 * j + 1][p];
            out4[(size_t)b0 * 8 + o] = make_float4(a.x, a.y, c.x, c.y);
        }
    }
}

extern "C" void kernel_launch(void* const* d_in, const int* in_sizes, int n_in,
                              void* d_out, int out_size)
{
    const float* x      = (const float*)d_in[0];
    const float* tables = (const float*)d_in[1];
    float4* out4        = (float4*)d_out;
    const int B = in_sizes[0] / 3;

    const int smem = TABLE_SZ * 2 * (int)sizeof(float);  // 131072 B
    cudaFuncSetAttribute(hashenc_kernel,
                         cudaFuncAttributeMaxDynamicSharedMemorySize, smem);

    pack_x_kernel<<<(B + 255) / 256, 256>>>((const float4*)x, B);

    dim3 grid(CHUNKS, NUM_LEVELS);
    hashenc_kernel<<<grid, THREADS, smem>>>(tables, B);

    transpose_kernel<<<(B + 255) / 256, 256>>>(out4, B);
}

// round 12
// speedup vs baseline: 1.1824x; 1.0099x over previous
#include <cuda_runtime.h>

#define NUM_LEVELS 16
#define TABLE_SZ   16384
#define CHUNKS     9
#define THREADS    1024
#define MAX_B      262144

// floor(16 * 1.38^l) computed in double precision, exactly representable in f32
__constant__ float c_res[NUM_LEVELS] = {
    16.f, 22.f, 30.f, 42.f, 58.f, 80.f, 110.f, 152.f,
    210.f, 290.f, 400.f, 553.f, 763.f, 1053.f, 1453.f, 2005.f
};

// Scratch (allocation-free rule: __device__ globals)
__device__ float4 g_xs[MAX_B];                       // packed positions (4 MB)
__device__ float2 g_scr[NUM_LEVELS * MAX_B];         // [level][b] features (33.5 MB)

extern __shared__ float2 s_tab[];  // main: 16384 float2 = 128 KB

// ---------------------------------------------------------------- pack x
__global__ __launch_bounds__(256)
void pack_x_kernel(const float4* __restrict__ x4, int B)
{
    __shared__ float sx[256 * 3];
    const int b0 = blockIdx.x * 256;
    const int t  = threadIdx.x;
    if (t < 192) {
        float4 v = x4[(size_t)(b0 * 3) / 4 + t];
        sx[4 * t + 0] = v.x; sx[4 * t + 1] = v.y;
        sx[4 * t + 2] = v.z; sx[4 * t + 3] = v.w;
    }
    __syncthreads();
    const int b = b0 + t;
    if (b < B)
        g_xs[b] = make_float4(sx[3 * t], sx[3 * t + 1], sx[3 * t + 2], 0.f);
}

// ---------------------------------------------------------------- main
__device__ __forceinline__ void hash_point(const float px, const float py,
                                           const float pz, const float res,
                                           float& ox, float& oy)
{
    // Interpolation weights use the UNSCALED position (faithful to source)
    const float wx = px - floorf(px);
    const float wy = py - floorf(py);
    const float wz = pz - floorf(pz);

    const float sx = res * px;
    const float sy = res * py;
    const float sz = res * pz;

    const int lx = __float2int_rd(sx);
    const int ly = __float2int_rd(sy);
    const int lz = __float2int_rd(sz);
    const int hx = __float2int_ru(sx);
    const int hy = __float2int_ru(sy);
    const int hz = __float2int_ru(sz);

    // int32 wraparound multiply == uint32 multiply (same bits);
    // python remainder by 16384 == & 16383 on two's complement
    const unsigned ay0 = 2654435761u * (unsigned)ly;
    const unsigned ay1 = 2654435761u * (unsigned)hy;
    const unsigned az0 = 805459861u  * (unsigned)lz;
    const unsigned az1 = 805459861u  * (unsigned)hz;

    const unsigned b00 = ay0 ^ az0;
    const unsigned b10 = ay1 ^ az0;
    const unsigned b01 = ay0 ^ az1;
    const unsigned b11 = ay1 ^ az1;
    const unsigned ux = (unsigned)lx;
    const unsigned vx = (unsigned)hx;

    // Corner order v0..v7: (0,0,0)(1,0,0)(1,1,0)(0,1,0)(0,0,1)(1,0,1)(1,1,1)(0,1,1)
    const float2 f0 = s_tab[(ux ^ b00) & 16383u];
    const float2 f1 = s_tab[(vx ^ b00) & 16383u];
    const float2 f2 = s_tab[(vx ^ b10) & 16383u];
    const float2 f3 = s_tab[(ux ^ b10) & 16383u];
    const float2 f4 = s_tab[(ux ^ b01) & 16383u];
    const float2 f5 = s_tab[(vx ^ b01) & 16383u];
    const float2 f6 = s_tab[(vx ^ b11) & 16383u];
    const float2 f7 = s_tab[(ux ^ b11) & 16383u];

    const float ex = 1.f - wx, ey = 1.f - wy, ez = 1.f - wz;
    const float w00 = ex * ey, w10 = wx * ey, w11 = wx * wy, w01 = ex * wy;
    const float c0 = w00 * ez, c1 = w10 * ez, c2 = w11 * ez, c3 = w01 * ez;
    const float c4 = w00 * wz, c5 = w10 * wz, c6 = w11 * wz, c7 = w01 * wz;

    float vxr = c0 * f0.x;
    vxr = fmaf(c1, f1.x, vxr);
    vxr = fmaf(c2, f2.x, vxr);
    vxr = fmaf(c3, f3.x, vxr);
    vxr = fmaf(c4, f4.x, vxr);
    vxr = fmaf(c5, f5.x, vxr);
    vxr = fmaf(c6, f6.x, vxr);
    vxr = fmaf(c7, f7.x, vxr);

    float vyr = c0 * f0.y;
    vyr = fmaf(c1, f1.y, vyr);
    vyr = fmaf(c2, f2.y, vyr);
    vyr = fmaf(c3, f3.y, vyr);
    vyr = fmaf(c4, f4.y, vyr);
    vyr = fmaf(c5, f5.y, vyr);
    vyr = fmaf(c6, f6.y, vyr);
    vyr = fmaf(c7, f7.y, vyr);

    ox = vxr;
    oy = vyr;
}

__global__ __launch_bounds__(THREADS, 1)
void hashenc_kernel(const float* __restrict__ tables, int B)
{
    const int level = blockIdx.y;

    // Cooperative fill of this level's table into shared memory (16B chunks)
    {
        const float4* src = reinterpret_cast<const float4*>(
            tables + (size_t)level * TABLE_SZ * 2);
        float4* dst = reinterpret_cast<float4*>(s_tab);
        #pragma unroll 4
        for (int i = threadIdx.x; i < TABLE_SZ / 2; i += THREADS)
            dst[i] = src[i];
    }
    __syncthreads();

    const float res = c_res[level];
    const int per   = (B + gridDim.x - 1) / gridDim.x;  // 29128 (even)
    const int start = blockIdx.x * per;
    const int end   = min(start + per, B);

    float2* __restrict__ scr = g_scr + (size_t)level * B;

    // Two consecutive points per thread; pairs never straddle chunk bounds
    for (int b = start + 2 * (int)threadIdx.x; b + 1 < end; b += 2 * THREADS) {
        const float4 p0 = g_xs[b];
        const float4 p1 = g_xs[b + 1];

        float ox0, oy0, ox1, oy1;
        hash_point(p0.x, p0.y, p0.z, res, ox0, oy0);
        hash_point(p1.x, p1.y, p1.z, res, ox1, oy1);

        // One coalesced STG.128 for the pair (b even -> 16B aligned)
        reinterpret_cast<float4*>(scr + b)[0] = make_float4(ox0, oy0, ox1, oy1);
    }
}

// ---------------------------------------------------------------- transpose
// 512 threads, tile = 256 points x 16 levels (32.9 KB smem) -> 4 blocks/SM
// = 2048 threads = 100% occupancy. Each thread loads 8 levels of one point
// (independent coalesced LDG.64, MLP=8), conflict-free STS.64, then 4
// coalesced STG.128 per thread.
__global__ __launch_bounds__(512)
void transpose_kernel(float4* __restrict__ out4, int B)
{
    __shared__ float2 s[NUM_LEVELS][257];
    const int b0   = blockIdx.x * 256;
    const int t    = threadIdx.x;          // 0..511
    const int p    = t & 255;              // point within tile
    const int l0   = (t >> 8) * 8;         // level group: 0 or 8
    const int b    = b0 + p;

    if (b < B) {
        float2 v[8];
        #pragma unroll
        for (int i = 0; i < 8; i++)
            v[i] = g_scr[(size_t)(l0 + i) * B + b];   // 8 independent loads
        #pragma unroll
        for (int i = 0; i < 8; i++)
            s[l0 + i][p] = v[i];                      // conflict-free STS.64
    }
    __syncthreads();

    // 256 points * 8 float4 = 2048 outputs, 4 per thread, coalesced
    #pragma unroll
    for (int i = 0; i < 4; i++) {
        int o  = i * 512 + t;              // 0..2047
        int pp = o >> 3;
        int j  = o & 7;
        if (b0 + pp < B) {
            float2 a = s[2 * j + 0][pp];
            float2 c = s[2 * j + 1][pp];
            out4[(size_t)b0 * 8 + o] = make_float4(a.x, a.y, c.x, c.y);
        }
    }
}

extern "C" void kernel_launch(void* const* d_in, const int* in_sizes, int n_in,
                              void* d_out, int out_size)
{
    const float* x      = (const float*)d_in[0];
    const float* tables = (const float*)d_in[1];
    float4* out4        = (float4*)d_out;
    const int B = in_sizes[0] / 3;

    const int smem = TABLE_SZ * 2 * (int)sizeof(float);  // 131072 B
    cudaFuncSetAttribute(hashenc_kernel,
                         cudaFuncAttributeMaxDynamicSharedMemorySize, smem);

    pack_x_kernel<<<(B + 255) / 256, 256>>>((const float4*)x, B);

    dim3 grid(CHUNKS, NUM_LEVELS);
    hashenc_kernel<<<grid, THREADS, smem>>>(tables, B);

    transpose_kernel<<<(B + 255) / 256, 512>>>(out4, B);
}